// round 12
// baseline (speedup 1.0000x reference)
#include <cuda_runtime.h>
#include <cuda_bf16.h>

// TopKPool: ONE kernel, 512 blocks. Phase 1 = R11's proven streaming scorer
// (4 blocks per batch row, 201 MB @ ~6.1 TB/s, one fence per block at the end).
// Per-row spin barrier (block 4b+q waits for g_count[b]==4), then phase 2 =
// R11's sliced tail run by the SAME warm blocks: redundant u64 candidate merge
// + 48-float4-column gather slice. Kills the dependent-launch boundary that
// cost a fixed ~6.5 us in every 2-kernel variant.
// Output layout: [pooled (B*D) | attn_weights (B*K)], fp32.

#define NEG_INF  (-1e30f)

constexpr int Bv = 128;
constexpr int Kv = 512;
constexpr int Dv = 768;
constexpr int D4 = Dv / 4;            // 192 float4 per row
constexpr int MAX_TOPK = 64;

constexpr int SPLIT = 4;              // segments (and column quarters) per row
constexpr int KSEG  = Kv / SPLIT;     // 128 K-rows per block
constexpr int CQ    = D4 / SPLIT;     // 48 float4 columns per block in phase 2
constexpr int T1    = 256;            // 8 warps

// packed candidates: key = (orderable(score) << 32) | ~idx   (max-key = best)
__device__ unsigned long long g_cand[Bv * SPLIT * MAX_TOPK];
__device__ int g_count[Bv];           // arrive counter (zero-init, self-reset)
__device__ int g_done[Bv];            // depart counter (zero-init, self-reset)

__device__ __forceinline__ int clamp_ksel(int k) {
    if (k < 1) k = 1;
    if (k > MAX_TOPK) k = MAX_TOPK;
    return k;
}

__device__ __forceinline__ unsigned long long pack_key(float v, int idx) {
    unsigned u = __float_as_uint(v);
    u = (u & 0x80000000u) ? ~u : (u | 0x80000000u);   // order-preserving map
    return ((unsigned long long)u << 32) | (unsigned)(~idx);   // tie -> lower idx
}

__global__ __launch_bounds__(T1)
void topkpool_fused(const float* __restrict__ emb,
                    const int*   __restrict__ mask,
                    const float* __restrict__ w,
                    const float* __restrict__ bias,
                    const int*   __restrict__ topk,
                    float*       __restrict__ out)
{
    __shared__ float s_sc[KSEG];
    __shared__ int   s_gk[MAX_TOPK];

    const int tid  = threadIdx.x;
    const int lane = tid & 31;
    const int wid  = tid >> 5;

    const int b   = blockIdx.x >> 2;
    const int seg = blockIdx.x & 3;           // also this block's column quarter
    const int k0  = seg * KSEG;

    float* out_pool = out;                    // (B, D)
    float* out_attn = out + (size_t)Bv * Dv;  // (B, K)

    const int   ksel = clamp_ksel(__ldg(&topk[0]));
    const float inv  = 1.f / (float)ksel;

    // ================= phase 1: streaming scorer (R11 K1, unchanged) =========
    {
        const float4* wg = (const float4*)w;
        const float4 w0 = __ldg(&wg[  0 + lane]);
        const float4 w1 = __ldg(&wg[ 32 + lane]);
        const float4 w2 = __ldg(&wg[ 64 + lane]);
        const float4 w3 = __ldg(&wg[ 96 + lane]);
        const float4 w4 = __ldg(&wg[128 + lane]);
        const float4 w5 = __ldg(&wg[160 + lane]);

        const float  bval = __ldg(&bias[0]);
        const float* eb   = emb + (size_t)b * Kv * Dv;

        for (int kk = wid; kk < KSEG / 2; kk += 8) {
            const int ka = kk;
            const int kb = kk + KSEG / 2;
            const float4* ra = (const float4*)(eb + (size_t)(k0 + ka) * Dv);
            const float4* rb = (const float4*)(eb + (size_t)(k0 + kb) * Dv);

            float4 a0 = __ldcs(&ra[  0 + lane]);
            float4 a1 = __ldcs(&ra[ 32 + lane]);
            float4 a2 = __ldcs(&ra[ 64 + lane]);
            float4 a3 = __ldcs(&ra[ 96 + lane]);
            float4 a4 = __ldcs(&ra[128 + lane]);
            float4 a5 = __ldcs(&ra[160 + lane]);
            float4 b0 = __ldcs(&rb[  0 + lane]);
            float4 b1 = __ldcs(&rb[ 32 + lane]);
            float4 b2 = __ldcs(&rb[ 64 + lane]);
            float4 b3 = __ldcs(&rb[ 96 + lane]);
            float4 b4 = __ldcs(&rb[128 + lane]);
            float4 b5 = __ldcs(&rb[160 + lane]);

            float acc_a = a0.x*w0.x + a0.y*w0.y + a0.z*w0.z + a0.w*w0.w
                        + a1.x*w1.x + a1.y*w1.y + a1.z*w1.z + a1.w*w1.w
                        + a2.x*w2.x + a2.y*w2.y + a2.z*w2.z + a2.w*w2.w
                        + a3.x*w3.x + a3.y*w3.y + a3.z*w3.z + a3.w*w3.w
                        + a4.x*w4.x + a4.y*w4.y + a4.z*w4.z + a4.w*w4.w
                        + a5.x*w5.x + a5.y*w5.y + a5.z*w5.z + a5.w*w5.w;
            float acc_b = b0.x*w0.x + b0.y*w0.y + b0.z*w0.z + b0.w*w0.w
                        + b1.x*w1.x + b1.y*w1.y + b1.z*w1.z + b1.w*w1.w
                        + b2.x*w2.x + b2.y*w2.y + b2.z*w2.z + b2.w*w2.w
                        + b3.x*w3.x + b3.y*w3.y + b3.z*w3.z + b3.w*w3.w
                        + b4.x*w4.x + b4.y*w4.y + b4.z*w4.z + b4.w*w4.w
                        + b5.x*w5.x + b5.y*w5.y + b5.z*w5.z + b5.w*w5.w;

            #pragma unroll
            for (int off = 16; off; off >>= 1) {
                acc_a += __shfl_xor_sync(0xFFFFFFFFu, acc_a, off);
                acc_b += __shfl_xor_sync(0xFFFFFFFFu, acc_b, off);
            }
            if (lane == 0) {
                float sa = acc_a + bval;
                float sb = acc_b + bval;
                if (__ldg(&mask[(size_t)b * Kv + k0 + ka]) == 0) sa = NEG_INF;
                if (__ldg(&mask[(size_t)b * Kv + k0 + kb]) == 0) sb = NEG_INF;
                s_sc[ka] = sa;
                s_sc[kb] = sb;
            }
        }

        // zero this block's chunk of the attn row (d_out is poisoned)
        for (int i = tid; i < KSEG; i += T1)
            out_attn[(size_t)b * Kv + k0 + i] = 0.f;

        __syncthreads();

        // per-segment top-ksel: tournament on packed u64 keys (warp 0)
        if (wid == 0) {
            unsigned long long key[4];
            #pragma unroll
            for (int j = 0; j < 4; j++)
                key[j] = pack_key(s_sc[lane + 32 * j], k0 + lane + 32 * j);

            unsigned long long* cd = g_cand + (size_t)(b * SPLIT + seg) * MAX_TOPK;

            for (int m = 0; m < ksel; m++) {
                unsigned long long best = key[0];
                #pragma unroll
                for (int j = 1; j < 4; j++) if (key[j] > best) best = key[j];
                #pragma unroll
                for (int off = 16; off; off >>= 1) {
                    unsigned long long o = __shfl_xor_sync(0xFFFFFFFFu, best, off);
                    if (o > best) best = o;
                }
                #pragma unroll
                for (int j = 0; j < 4; j++) if (key[j] == best) key[j] = 0ull;
                if (lane == 0) cd[m] = best;
            }
        }
    }

    // ================= per-row spin barrier ==================================
    __threadfence();                    // candidates + attn zeros visible
    __syncthreads();
    if (tid == 0) {
        atomicAdd(&g_count[b], 1);
        while (atomicAdd(&g_count[b], 0) < SPLIT)
            __nanosleep(32);
    }
    __syncthreads();

    // ================= phase 2: sliced tail (same blocks, warm SMs) ==========
    {
        const int C = SPLIT * ksel;
        const unsigned long long* cd = g_cand + (size_t)b * SPLIT * MAX_TOPK;

        if (wid == 0) {
            if (C <= 32) {
                unsigned long long key = 0ull;
                if (lane < C) {
                    int sg = lane / ksel, m = lane - sg * ksel;
                    key = __ldcg(&cd[(size_t)sg * MAX_TOPK + m]);
                }
                for (int m = 0; m < ksel; m++) {
                    unsigned long long best = key;
                    #pragma unroll
                    for (int off = 16; off; off >>= 1) {
                        unsigned long long o = __shfl_xor_sync(0xFFFFFFFFu, best, off);
                        if (o > best) best = o;
                    }
                    if (key == best) key = 0ull;
                    if (lane == 0) s_gk[m] = (int)(~(unsigned)(best & 0xFFFFFFFFull));
                }
            } else {
                unsigned long long key[8];
                #pragma unroll
                for (int j = 0; j < 8; j++) {
                    int n = lane + 32 * j;
                    if (n < C) {
                        int sg = n / ksel, m = n - sg * ksel;
                        key[j] = __ldcg(&cd[(size_t)sg * MAX_TOPK + m]);
                    } else key[j] = 0ull;
                }
                for (int m = 0; m < ksel; m++) {
                    unsigned long long best = key[0];
                    #pragma unroll
                    for (int j = 1; j < 8; j++) if (key[j] > best) best = key[j];
                    #pragma unroll
                    for (int off = 16; off; off >>= 1) {
                        unsigned long long o = __shfl_xor_sync(0xFFFFFFFFu, best, off);
                        if (o > best) best = o;
                    }
                    #pragma unroll
                    for (int j = 0; j < 8; j++) if (key[j] == best) key[j] = 0ull;
                    if (lane == 0) s_gk[m] = (int)(~(unsigned)(best & 0xFFFFFFFFull));
                }
            }
        }
        __syncthreads();

        // indicators: only quarter 0 writes (row fully zeroed pre-barrier)
        if (seg == 0 && tid < ksel)
            out_attn[(size_t)b * Kv + s_gk[tid]] = inv;

        // sliced gather: this block owns float4 columns [seg*CQ, (seg+1)*CQ)
        if (tid < CQ) {
            const float4* ebv = (const float4*)(emb + (size_t)b * Kv * Dv);
            const int col = seg * CQ + tid;
            float4 sum = make_float4(0.f, 0.f, 0.f, 0.f);
            if (ksel == 8) {
                int ix[8];
                #pragma unroll
                for (int m = 0; m < 8; m++) ix[m] = s_gk[m];
                #pragma unroll
                for (int m = 0; m < 8; m++) {
                    float4 e = __ldg(&ebv[(size_t)ix[m] * D4 + col]);
                    sum.x += e.x; sum.y += e.y; sum.z += e.z; sum.w += e.w;
                }
            } else {
                #pragma unroll 4
                for (int m = 0; m < ksel; m++) {
                    float4 e = __ldg(&ebv[(size_t)s_gk[m] * D4 + col]);
                    sum.x += e.x; sum.y += e.y; sum.z += e.z; sum.w += e.w;
                }
            }
            float4 r = make_float4(sum.x * inv, sum.y * inv, sum.z * inv, sum.w * inv);
            ((float4*)(out_pool + (size_t)b * Dv))[col] = r;
        }
    }

    // ================= depart + counter self-reset for graph replay ==========
    __syncthreads();
    if (tid == 0) {
        int old = atomicAdd(&g_done[b], 1);
        if (old == SPLIT - 1) {         // last departer resets both counters
            g_count[b] = 0;
            g_done[b]  = 0;
        }
    }
}

extern "C" void kernel_launch(void* const* d_in, const int* in_sizes, int n_in,
                              void* d_out, int out_size)
{
    const float* emb  = (const float*)d_in[0];
    const int*   mask = (const int*)  d_in[1];
    const float* w    = (const float*)d_in[2];
    const float* bias = (const float*)d_in[3];
    const int*   topk = (const int*)  d_in[4];
    float*       out  = (float*)d_out;
    (void)in_sizes; (void)n_in; (void)out_size;

    topkpool_fused<<<Bv * SPLIT, T1>>>(emb, mask, w, bias, topk, out);
}